// round 1
// baseline (speedup 1.0000x reference)
#include <cuda_runtime.h>
#include <cuda_bf16.h>

#define N_NODES 50000
#define N_EDGES 800000
#define NF 256
#define TE 64          // tile rows (edges / nodes) per CTA
#define AS 260         // smem A row stride (padded, multiple of 4)
#define THREADS 256

typedef unsigned long long ull;

// ----------------------------- device scratch -----------------------------
__device__ float g_P[N_NODES * NF];
__device__ float g_Q[N_NODES * NF];
__device__ float g_agg[N_NODES * NF];
__device__ float g_csum[N_NODES * 3];
__device__ float g_cnt[N_NODES];
__device__ float g_We1aT[NF * NF];
__device__ float g_We1bT[NF * NF];
__device__ float g_we1last[NF];
__device__ float g_We2T[NF * NF];
__device__ float g_Wc1T[NF * NF];
__device__ float g_Wn1T[512 * NF];
__device__ float g_Wn2T[NF * NF];

// ----------------------------- helpers -----------------------------
__device__ __forceinline__ float silu(float x) {
    return x / (1.0f + __expf(-x));
}

__device__ __forceinline__ ull pack2(float x, float y) {
    ull r;
    asm("mov.b64 %0, {%1, %2};" : "=l"(r) : "f"(x), "f"(y));
    return r;
}
__device__ __forceinline__ float2 unpack2(ull v) {
    float2 f;
    asm("mov.b64 {%0, %1}, %2;" : "=f"(f.x), "=f"(f.y) : "l"(v));
    return f;
}
// packed fp32x2 FMA: acc = a*b + acc (2 exact fp32 FMAs per instruction)
__device__ __forceinline__ void fma2(ull& acc, ull a, ull b) {
    asm("fma.rn.f32x2 %0, %1, %2, %0;" : "+l"(acc) : "l"(a), "l"(b));
}

__device__ __forceinline__ void zero_acc(ull acc[4][8]) {
#pragma unroll
    for (int i = 0; i < 4; i++)
#pragma unroll
        for (int j = 0; j < 8; j++) acc[i][j] = 0ull;
}

// C[64][256] += A[64][K](smem, stride AS) * Bt[K][256](global, row-major).
// Thread (ty,tx): rows ty*4+i, column-pairs p = jj*16+tx (cols 2p, 2p+1).
__device__ __forceinline__ void gemm_acc(ull acc[4][8],
                                         const float* __restrict__ Bt,
                                         const float* As, int K,
                                         float* BsF, int ty, int tx) {
    const int tid = threadIdx.x;
    for (int kb = 0; kb < K; kb += 32) {
        __syncthreads();  // previous consumers of BsF done / A ready
        const float4* src = (const float4*)(Bt + kb * NF);
        float4* dst = (float4*)BsF;
#pragma unroll
        for (int it = 0; it < 8; it++) {
            int l = tid + it * THREADS;
            dst[l] = src[l];
        }
        __syncthreads();
        const ull* Bs2 = (const ull*)BsF;
#pragma unroll
        for (int k = 0; k < 32; k++) {
            ull a[4];
#pragma unroll
            for (int i = 0; i < 4; i++) {
                float av = As[(ty * 4 + i) * AS + kb + k];
                a[i] = pack2(av, av);
            }
#pragma unroll
            for (int jj = 0; jj < 8; jj++) {
                ull b = Bs2[k * 128 + jj * 16 + tx];
#pragma unroll
                for (int i = 0; i < 4; i++) fma2(acc[i][jj], a[i], b);
            }
        }
    }
}

// epilogue: Cs[e][c] = silu(acc + bias[c])   (Cs smem, stride AS)
__device__ __forceinline__ void epi_store_silu(ull acc[4][8],
                                               const float* __restrict__ bias,
                                               float* Cs, int ty, int tx) {
    const float2* b2 = (const float2*)bias;
#pragma unroll
    for (int i = 0; i < 4; i++) {
        int e = ty * 4 + i;
#pragma unroll
        for (int jj = 0; jj < 8; jj++) {
            int p = jj * 16 + tx;
            float2 v = unpack2(acc[i][jj]);
            float2 b = b2[p];
            ((float2*)(Cs + e * AS))[p] = make_float2(silu(v.x + b.x), silu(v.y + b.y));
        }
    }
}

// epilogue: phi[e] += sum_c silu(acc + bc1[c]) * wc2[c]   (phi in smem)
__device__ __forceinline__ void epi_phi(ull acc[4][8],
                                        const float* __restrict__ bc1,
                                        const float* __restrict__ wc2,
                                        float* phi_s, int ty, int tx) {
    const float2* b2 = (const float2*)bc1;
    const float2* w2 = (const float2*)wc2;
#pragma unroll
    for (int i = 0; i < 4; i++) {
        int e = ty * 4 + i;
        float s = 0.f;
#pragma unroll
        for (int jj = 0; jj < 8; jj++) {
            int p = jj * 16 + tx;
            float2 v = unpack2(acc[i][jj]);
            float2 b = b2[p];
            float2 w = w2[p];
            s += silu(v.x + b.x) * w.x + silu(v.y + b.y) * w.y;
        }
        atomicAdd(&phi_s[e], s);
    }
}

// epilogue: store raw acc to global Cg[n][256] with row guard
__device__ __forceinline__ void epi_store_g(ull acc[4][8], float* __restrict__ Cg,
                                            int nb, int ty, int tx) {
#pragma unroll
    for (int i = 0; i < 4; i++) {
        int n = nb + ty * 4 + i;
        if (n < N_NODES) {
#pragma unroll
            for (int jj = 0; jj < 8; jj++) {
                int p = jj * 16 + tx;
                ((float2*)(Cg + (size_t)n * NF))[p] = unpack2(acc[i][jj]);
            }
        }
    }
}

// epilogue: out[n][c] = acc + bn2[c] + h[n][c]   (residual)
__device__ __forceinline__ void epi_node_out(ull acc[4][8],
                                             const float* __restrict__ bn2,
                                             const float* __restrict__ h,
                                             float* __restrict__ out,
                                             int nb, int ty, int tx) {
    const float2* b2 = (const float2*)bn2;
#pragma unroll
    for (int i = 0; i < 4; i++) {
        int n = nb + ty * 4 + i;
        if (n < N_NODES) {
            const float2* h2 = (const float2*)(h + (size_t)n * NF);
            float2* o2 = (float2*)(out + (size_t)n * NF);
#pragma unroll
            for (int jj = 0; jj < 8; jj++) {
                int p = jj * 16 + tx;
                float2 v = unpack2(acc[i][jj]);
                float2 b = b2[p];
                float2 hh = h2[p];
                o2[p] = make_float2(v.x + b.x + hh.x, v.y + b.y + hh.y);
            }
        }
    }
}

// ----------------------------- kernels -----------------------------

__global__ void zero_kernel() {
    int i = blockIdx.x * blockDim.x + threadIdx.x;
    int tot4 = (N_NODES * NF) / 4;
    if (i < tot4) ((float4*)g_agg)[i] = make_float4(0.f, 0.f, 0.f, 0.f);
    if (i < N_NODES) {
        g_cnt[i] = 0.f;
        g_csum[i * 3 + 0] = 0.f;
        g_csum[i * 3 + 1] = 0.f;
        g_csum[i * 3 + 2] = 0.f;
    }
}

__global__ void prep_kernel(const float* __restrict__ We1, const float* __restrict__ We2,
                            const float* __restrict__ Wc1, const float* __restrict__ Wn1,
                            const float* __restrict__ Wn2) {
    int idx = blockIdx.x * blockDim.x + threadIdx.x;  // over 512*256
    if (idx >= 512 * NF) return;
    int k = idx / NF, c = idx % NF;
    if (k < NF) {
        g_We1aT[k * NF + c] = We1[c * 513 + k];
        g_We1bT[k * NF + c] = We1[c * 513 + NF + k];
        g_We2T[k * NF + c] = We2[c * NF + k];
        g_Wc1T[k * NF + c] = Wc1[c * NF + k];
        g_Wn2T[k * NF + c] = Wn2[c * NF + k];
        if (k == 0) g_we1last[c] = We1[c * 513 + 512];
    }
    g_Wn1T[k * NF + c] = Wn1[c * 512 + k];
}

// P = h @ We1a^T ; Q = h @ We1b^T
__global__ __launch_bounds__(THREADS, 1) void pq_kernel(const float* __restrict__ h) {
    extern __shared__ float sm[];
    float* At = sm;              // 64*AS
    float* Bs = sm + TE * AS;    // 8192 floats
    int tid = threadIdx.x, ty = tid >> 4, tx = tid & 15;
    int nb = blockIdx.x * TE;
#pragma unroll
    for (int it = 0; it < 16; it++) {
        int l = tid + it * THREADS;  // 64 rows * 64 float4
        int r = l >> 6, c4 = l & 63;
        int n = nb + r;
        float4 v = (n < N_NODES) ? ((const float4*)(h + (size_t)n * NF))[c4]
                                 : make_float4(0.f, 0.f, 0.f, 0.f);
        *(float4*)(At + r * AS + c4 * 4) = v;
    }
    ull acc[4][8];
    zero_acc(acc);
    gemm_acc(acc, g_We1aT, At, NF, Bs, ty, tx);
    epi_store_g(acc, g_P, nb, ty, tx);
    zero_acc(acc);
    gemm_acc(acc, g_We1bT, At, NF, Bs, ty, tx);
    epi_store_g(acc, g_Q, nb, ty, tx);
}

// fused per-edge pipeline: m -> edge_feat -> phi -> atomics
__global__ __launch_bounds__(THREADS, 1) void edge_kernel(
    const int* __restrict__ ei, const float* __restrict__ coord,
    const float* __restrict__ be1, const float* __restrict__ be2,
    const float* __restrict__ bc1, const float* __restrict__ wc2) {
    extern __shared__ float sm[];
    float* m = sm;                     // 64*AS
    float* ef = sm + TE * AS;          // 64*AS
    float* Bs = ef + TE * AS;          // 8192
    float* cd = Bs + 8192;             // 192
    float* radial = cd + 192;          // 64
    float* phi = radial + 64;          // 64
    int* rows = (int*)(phi + 64);      // 64
    int* colsI = rows + 64;            // 64

    int tid = threadIdx.x, ty = tid >> 4, tx = tid & 15;
    int eb = blockIdx.x * TE;

    if (tid < TE) {
        int e = eb + tid;
        int r = ei[e], c = ei[N_EDGES + e];
        rows[tid] = r;
        colsI[tid] = c;
        float dx = coord[r * 3 + 0] - coord[c * 3 + 0];
        float dy = coord[r * 3 + 1] - coord[c * 3 + 1];
        float dz = coord[r * 3 + 2] - coord[c * 3 + 2];
        cd[tid * 3 + 0] = dx;
        cd[tid * 3 + 1] = dy;
        cd[tid * 3 + 2] = dz;
        radial[tid] = dx * dx + dy * dy + dz * dz;
        phi[tid] = 0.f;
    }
    __syncthreads();

    // stage B: m[e][c] = silu(P[row] + Q[col] + radial*we1last + be1)
    float wl = g_we1last[tid];
    float b1 = be1[tid];
#pragma unroll 8
    for (int e = 0; e < TE; e++) {
        int r = rows[e], c = colsI[e];
        float val = g_P[(size_t)r * NF + tid] + g_Q[(size_t)c * NF + tid] + radial[e] * wl + b1;
        m[e * AS + tid] = silu(val);
    }
    __syncthreads();

    ull acc[4][8];
    // GEMM2: edge_feat = silu(m @ We2^T + be2)
    zero_acc(acc);
    gemm_acc(acc, g_We2T, m, NF, Bs, ty, tx);
    epi_store_silu(acc, be2, ef, ty, tx);

    // GEMM3 (fused coord mlp): phi = (silu(ef @ Wc1^T + bc1)) @ wc2
    zero_acc(acc);
    gemm_acc(acc, g_Wc1T, ef, NF, Bs, ty, tx);  // internal syncs cover ef writes
    epi_phi(acc, bc1, wc2, phi, ty, tx);
    __syncthreads();

    // coord trans atomics
    if (tid < TE) {
        float p = phi[tid];
        int r = rows[tid];
        atomicAdd(&g_csum[r * 3 + 0], cd[tid * 3 + 0] * p);
        atomicAdd(&g_csum[r * 3 + 1], cd[tid * 3 + 1] * p);
        atomicAdd(&g_csum[r * 3 + 2], cd[tid * 3 + 2] * p);
        atomicAdd(&g_cnt[r], 1.0f);
    }
    // agg atomics (coalesced rows, no return -> REDG)
#pragma unroll 4
    for (int e = 0; e < TE; e++) {
        atomicAdd(&g_agg[(size_t)rows[e] * NF + tid], ef[e * AS + tid]);
    }
}

// node MLP: h_out = h + Wn2 @ silu(Wn1 @ [h, agg] + bn1) + bn2
__global__ __launch_bounds__(THREADS, 1) void node_kernel(
    const float* __restrict__ h, const float* __restrict__ bn1,
    const float* __restrict__ bn2, float* __restrict__ out) {
    extern __shared__ float sm[];
    float* Ah = sm;
    float* Ag = sm + TE * AS;
    float* Bs = Ag + TE * AS;
    int tid = threadIdx.x, ty = tid >> 4, tx = tid & 15;
    int nb = blockIdx.x * TE;
#pragma unroll
    for (int it = 0; it < 16; it++) {
        int l = tid + it * THREADS;
        int r = l >> 6, c4 = l & 63;
        int n = nb + r;
        float4 vh, va;
        if (n < N_NODES) {
            vh = ((const float4*)(h + (size_t)n * NF))[c4];
            va = ((const float4*)(g_agg + (size_t)n * NF))[c4];
        } else {
            vh = make_float4(0.f, 0.f, 0.f, 0.f);
            va = vh;
        }
        *(float4*)(Ah + r * AS + c4 * 4) = vh;
        *(float4*)(Ag + r * AS + c4 * 4) = va;
    }
    ull acc[4][8];
    zero_acc(acc);
    gemm_acc(acc, g_Wn1T, Ah, NF, Bs, ty, tx);             // k = 0..255 (h part)
    gemm_acc(acc, g_Wn1T + NF * NF, Ag, NF, Bs, ty, tx);   // k = 256..511 (agg part)
    epi_store_silu(acc, bn1, Ah, ty, tx);                  // hidden -> reuse Ah
    zero_acc(acc);
    gemm_acc(acc, g_Wn2T, Ah, NF, Bs, ty, tx);             // internal syncs cover Ah writes
    epi_node_out(acc, bn2, h, out, nb, ty, tx);
}

__global__ void coord_kernel(const float* __restrict__ coord, float* __restrict__ out) {
    int n = blockIdx.x * blockDim.x + threadIdx.x;
    if (n >= N_NODES) return;
    float c = fmaxf(g_cnt[n], 1.0f);
    size_t base = (size_t)N_NODES * NF;
    out[base + n * 3 + 0] = coord[n * 3 + 0] + g_csum[n * 3 + 0] / c;
    out[base + n * 3 + 1] = coord[n * 3 + 1] + g_csum[n * 3 + 1] / c;
    out[base + n * 3 + 2] = coord[n * 3 + 2] + g_csum[n * 3 + 2] / c;
}

// ----------------------------- host -----------------------------
extern "C" void kernel_launch(void* const* d_in, const int* in_sizes, int n_in,
                              void* d_out, int out_size) {
    const float* h = (const float*)d_in[0];
    const int* ei = (const int*)d_in[1];
    const float* coord = (const float*)d_in[2];
    const float* We1 = (const float*)d_in[3];
    const float* be1 = (const float*)d_in[4];
    const float* We2 = (const float*)d_in[5];
    const float* be2 = (const float*)d_in[6];
    const float* Wn1 = (const float*)d_in[7];
    const float* bn1 = (const float*)d_in[8];
    const float* Wn2 = (const float*)d_in[9];
    const float* bn2 = (const float*)d_in[10];
    const float* Wc1 = (const float*)d_in[11];
    const float* bc1 = (const float*)d_in[12];
    const float* Wc2 = (const float*)d_in[13];
    float* out = (float*)d_out;

    const int EDGE_SMEM = (TE * AS * 2 + 8192 + 192 + 64 + 64) * 4 + 128 * 4;
    const int NODE_SMEM = (TE * AS * 2 + 8192) * 4;
    const int PQ_SMEM = (TE * AS + 8192) * 4;

    cudaFuncSetAttribute(edge_kernel, cudaFuncAttributeMaxDynamicSharedMemorySize, EDGE_SMEM);
    cudaFuncSetAttribute(node_kernel, cudaFuncAttributeMaxDynamicSharedMemorySize, NODE_SMEM);
    cudaFuncSetAttribute(pq_kernel, cudaFuncAttributeMaxDynamicSharedMemorySize, PQ_SMEM);

    zero_kernel<<<(N_NODES * NF / 4 + 255) / 256, 256>>>();
    prep_kernel<<<(512 * NF + 255) / 256, 256>>>(We1, We2, Wc1, Wn1, Wn2);
    pq_kernel<<<(N_NODES + TE - 1) / TE, THREADS, PQ_SMEM>>>(h);
    edge_kernel<<<N_EDGES / TE, THREADS, EDGE_SMEM>>>(ei, coord, be1, be2, bc1, Wc2);
    node_kernel<<<(N_NODES + TE - 1) / TE, THREADS, NODE_SMEM>>>(h, bn1, bn2, out);
    coord_kernel<<<(N_NODES + 255) / 256, 256>>>(coord, out);
}

// round 9
// speedup vs baseline: 1.3133x; 1.3133x over previous
#include <cuda_runtime.h>
#include <cuda_bf16.h>

#define N_NODES 50000
#define N_EDGES 800000
#define NF 256
#define TE 64          // tile rows (edges / nodes) per CTA
#define AS 260         // smem A row stride (padded, 1040B = 16B aligned rows)
#define THREADS 256

typedef unsigned long long ull;

// ----------------------------- device scratch -----------------------------
// __align__(16): all of these are accessed via float4 / red.global.add.v4.f32;
// wide-operand misalignment is a hardware trap (err715) on sm_103a.
__device__ __align__(16) float g_P[N_NODES * NF];
__device__ __align__(16) float g_Q[N_NODES * NF];
__device__ __align__(16) float g_agg[N_NODES * NF];
__device__ __align__(16) float g_csum[N_NODES * 3];
__device__ __align__(16) float g_cnt[N_NODES];
__device__ __align__(16) float g_We1aT[NF * NF];
__device__ __align__(16) float g_We1bT[NF * NF];
__device__ __align__(16) float g_we1last[NF];
__device__ __align__(16) float g_We2T[NF * NF];
__device__ __align__(16) float g_Wc1T[NF * NF];
__device__ __align__(16) float g_Wn1T[512 * NF];
__device__ __align__(16) float g_Wn2T[NF * NF];

// ----------------------------- helpers -----------------------------
__device__ __forceinline__ float silu(float x) {
    return x / (1.0f + __expf(-x));
}

__device__ __forceinline__ ull pack2(float x, float y) {
    ull r;
    asm("mov.b64 %0, {%1, %2};" : "=l"(r) : "f"(x), "f"(y));
    return r;
}
__device__ __forceinline__ float2 unpack2(ull v) {
    float2 f;
    asm("mov.b64 {%0, %1}, %2;" : "=f"(f.x), "=f"(f.y) : "l"(v));
    return f;
}
// packed fp32x2 FMA: acc = a*b + acc (2 exact fp32 FMAs per instruction)
__device__ __forceinline__ void fma2(ull& acc, ull a, ull b) {
    asm("fma.rn.f32x2 %0, %1, %2, %0;" : "+l"(acc) : "l"(a), "l"(b));
}

// vectorized no-return global reduction (4 floats, one L2 atomic op)
__device__ __forceinline__ void red4(float* p, float4 v) {
    asm volatile("red.global.add.v4.f32 [%0], {%1, %2, %3, %4};"
                 :: "l"(p), "f"(v.x), "f"(v.y), "f"(v.z), "f"(v.w) : "memory");
}

__device__ __forceinline__ void zero_acc(ull acc[4][8]) {
#pragma unroll
    for (int i = 0; i < 4; i++)
#pragma unroll
        for (int j = 0; j < 8; j++) acc[i][j] = 0ull;
}

// C[64][256] += A[64][K](smem, stride AS) * Bt[K][256](global, row-major).
// Thread (ty,tx): rows ty*4+i, column-pairs p = jj*16+tx (cols 2p, 2p+1).
__device__ __forceinline__ void gemm_acc(ull acc[4][8],
                                         const float* __restrict__ Bt,
                                         const float* As, int K,
                                         float* BsF, int ty, int tx) {
    const int tid = threadIdx.x;
    for (int kb = 0; kb < K; kb += 32) {
        __syncthreads();  // previous consumers of BsF done / A ready
        const float4* src = (const float4*)(Bt + kb * NF);
        float4* dst = (float4*)BsF;
#pragma unroll
        for (int it = 0; it < 8; it++) {
            int l = tid + it * THREADS;
            dst[l] = src[l];
        }
        __syncthreads();
        const ull* Bs2 = (const ull*)BsF;
#pragma unroll
        for (int k = 0; k < 32; k++) {
            ull a[4];
#pragma unroll
            for (int i = 0; i < 4; i++) {
                float av = As[(ty * 4 + i) * AS + kb + k];
                a[i] = pack2(av, av);
            }
#pragma unroll
            for (int jj = 0; jj < 8; jj++) {
                ull b = Bs2[k * 128 + jj * 16 + tx];
#pragma unroll
                for (int i = 0; i < 4; i++) fma2(acc[i][jj], a[i], b);
            }
        }
    }
}

// epilogue: Cs[e][c] = silu(acc + bias[c])   (Cs smem, stride AS)
__device__ __forceinline__ void epi_store_silu(ull acc[4][8],
                                               const float* __restrict__ bias,
                                               float* Cs, int ty, int tx) {
    const float2* b2 = (const float2*)bias;
#pragma unroll
    for (int i = 0; i < 4; i++) {
        int e = ty * 4 + i;
#pragma unroll
        for (int jj = 0; jj < 8; jj++) {
            int p = jj * 16 + tx;
            float2 v = unpack2(acc[i][jj]);
            float2 b = b2[p];
            ((float2*)(Cs + e * AS))[p] = make_float2(silu(v.x + b.x), silu(v.y + b.y));
        }
    }
}

// epilogue: phi[e] += sum_c silu(acc + bc1[c]) * wc2[c]   (phi in smem)
__device__ __forceinline__ void epi_phi(ull acc[4][8],
                                        const float* __restrict__ bc1,
                                        const float* __restrict__ wc2,
                                        float* phi_s, int ty, int tx) {
    const float2* b2 = (const float2*)bc1;
    const float2* w2 = (const float2*)wc2;
#pragma unroll
    for (int i = 0; i < 4; i++) {
        int e = ty * 4 + i;
        float s = 0.f;
#pragma unroll
        for (int jj = 0; jj < 8; jj++) {
            int p = jj * 16 + tx;
            float2 v = unpack2(acc[i][jj]);
            float2 b = b2[p];
            float2 w = w2[p];
            s += silu(v.x + b.x) * w.x + silu(v.y + b.y) * w.y;
        }
        atomicAdd(&phi_s[e], s);
    }
}

// epilogue: store raw acc to global Cg[n][256] with row guard
__device__ __forceinline__ void epi_store_g(ull acc[4][8], float* __restrict__ Cg,
                                            int nb, int ty, int tx) {
#pragma unroll
    for (int i = 0; i < 4; i++) {
        int n = nb + ty * 4 + i;
        if (n < N_NODES) {
#pragma unroll
            for (int jj = 0; jj < 8; jj++) {
                int p = jj * 16 + tx;
                ((float2*)(Cg + (size_t)n * NF))[p] = unpack2(acc[i][jj]);
            }
        }
    }
}

// epilogue: out[n][c] = acc + bn2[c] + h[n][c]   (residual)
__device__ __forceinline__ void epi_node_out(ull acc[4][8],
                                             const float* __restrict__ bn2,
                                             const float* __restrict__ h,
                                             float* __restrict__ out,
                                             int nb, int ty, int tx) {
    const float2* b2 = (const float2*)bn2;
#pragma unroll
    for (int i = 0; i < 4; i++) {
        int n = nb + ty * 4 + i;
        if (n < N_NODES) {
            const float2* h2 = (const float2*)(h + (size_t)n * NF);
            float2* o2 = (float2*)(out + (size_t)n * NF);
#pragma unroll
            for (int jj = 0; jj < 8; jj++) {
                int p = jj * 16 + tx;
                float2 v = unpack2(acc[i][jj]);
                float2 b = b2[p];
                float2 hh = h2[p];
                o2[p] = make_float2(v.x + b.x + hh.x, v.y + b.y + hh.y);
            }
        }
    }
}

// ----------------------------- kernels -----------------------------

__global__ void zero_kernel() {
    int i = blockIdx.x * blockDim.x + threadIdx.x;
    int tot4 = (N_NODES * NF) / 4;
    if (i < tot4) ((float4*)g_agg)[i] = make_float4(0.f, 0.f, 0.f, 0.f);
    if (i < N_NODES) {
        g_cnt[i] = 0.f;
        g_csum[i * 3 + 0] = 0.f;
        g_csum[i * 3 + 1] = 0.f;
        g_csum[i * 3 + 2] = 0.f;
    }
}

__global__ void prep_kernel(const float* __restrict__ We1, const float* __restrict__ We2,
                            const float* __restrict__ Wc1, const float* __restrict__ Wn1,
                            const float* __restrict__ Wn2) {
    int idx = blockIdx.x * blockDim.x + threadIdx.x;  // over 512*256
    if (idx >= 512 * NF) return;
    int k = idx / NF, c = idx % NF;
    if (k < NF) {
        g_We1aT[k * NF + c] = We1[c * 513 + k];
        g_We1bT[k * NF + c] = We1[c * 513 + NF + k];
        g_We2T[k * NF + c] = We2[c * NF + k];
        g_Wc1T[k * NF + c] = Wc1[c * NF + k];
        g_Wn2T[k * NF + c] = Wn2[c * NF + k];
        if (k == 0) g_we1last[c] = We1[c * 513 + 512];
    }
    g_Wn1T[k * NF + c] = Wn1[c * 512 + k];
}

// P = h @ We1a^T ; Q = h @ We1b^T
__global__ __launch_bounds__(THREADS, 2) void pq_kernel(const float* __restrict__ h) {
    extern __shared__ float sm[];
    float* At = sm;              // 64*AS
    float* Bs = sm + TE * AS;    // 8192 floats
    int tid = threadIdx.x, ty = tid >> 4, tx = tid & 15;
    int nb = blockIdx.x * TE;
#pragma unroll
    for (int it = 0; it < 16; it++) {
        int l = tid + it * THREADS;  // 64 rows * 64 float4
        int r = l >> 6, c4 = l & 63;
        int n = nb + r;
        float4 v = (n < N_NODES) ? ((const float4*)(h + (size_t)n * NF))[c4]
                                 : make_float4(0.f, 0.f, 0.f, 0.f);
        *(float4*)(At + r * AS + c4 * 4) = v;
    }
    ull acc[4][8];
    zero_acc(acc);
    gemm_acc(acc, g_We1aT, At, NF, Bs, ty, tx);
    epi_store_g(acc, g_P, nb, ty, tx);
    zero_acc(acc);
    gemm_acc(acc, g_We1bT, At, NF, Bs, ty, tx);
    epi_store_g(acc, g_Q, nb, ty, tx);
}

// fused per-edge pipeline: m -> edge_feat -> phi -> atomics
// Single A-tile: GEMM2 reads m from At, its epilogue overwrites At with ef
// (m is dead after GEMM2's accumulation), GEMM3 reads ef from At.
__global__ __launch_bounds__(THREADS, 2) void edge_kernel(
    const int* __restrict__ ei, const float* __restrict__ coord,
    const float* __restrict__ be1, const float* __restrict__ be2,
    const float* __restrict__ bc1, const float* __restrict__ wc2) {
    extern __shared__ float sm[];
    float* At = sm;                    // 64*AS (m, then ef)
    float* Bs = At + TE * AS;          // 8192
    float* cd = Bs + 8192;             // 192
    float* radial = cd + 192;          // 64
    float* phi = radial + 64;          // 64
    int* rows = (int*)(phi + 64);      // 64
    int* colsI = rows + 64;            // 64

    int tid = threadIdx.x, ty = tid >> 4, tx = tid & 15;
    int eb = blockIdx.x * TE;

    if (tid < TE) {
        int e = eb + tid;
        int r = ei[e], c = ei[N_EDGES + e];
        rows[tid] = r;
        colsI[tid] = c;
        float dx = coord[r * 3 + 0] - coord[c * 3 + 0];
        float dy = coord[r * 3 + 1] - coord[c * 3 + 1];
        float dz = coord[r * 3 + 2] - coord[c * 3 + 2];
        cd[tid * 3 + 0] = dx;
        cd[tid * 3 + 1] = dy;
        cd[tid * 3 + 2] = dz;
        radial[tid] = dx * dx + dy * dy + dz * dz;
        phi[tid] = 0.f;
    }
    __syncthreads();

    // stage B: m[e][c] = silu(P[row] + Q[col] + radial*we1last + be1)
    float wl = g_we1last[tid];
    float b1 = be1[tid];
#pragma unroll 8
    for (int e = 0; e < TE; e++) {
        int r = rows[e], c = colsI[e];
        float val = g_P[(size_t)r * NF + tid] + g_Q[(size_t)c * NF + tid] + radial[e] * wl + b1;
        At[e * AS + tid] = silu(val);
    }
    // gemm_acc's leading __syncthreads orders these writes before A reads

    ull acc[4][8];
    // GEMM2: edge_feat = silu(m @ We2^T + be2)
    zero_acc(acc);
    gemm_acc(acc, g_We2T, At, NF, Bs, ty, tx);
    __syncthreads();                      // all reads of m done before overwrite
    epi_store_silu(acc, be2, At, ty, tx); // ef into same tile

    // GEMM3 (fused coord mlp): phi = (silu(ef @ Wc1^T + bc1)) @ wc2
    zero_acc(acc);
    gemm_acc(acc, g_Wc1T, At, NF, Bs, ty, tx);  // leading sync covers ef writes
    epi_phi(acc, bc1, wc2, phi, ty, tx);
    __syncthreads();

    // coord trans atomics
    if (tid < TE) {
        float p = phi[tid];
        int r = rows[tid];
        atomicAdd(&g_csum[r * 3 + 0], cd[tid * 3 + 0] * p);
        atomicAdd(&g_csum[r * 3 + 1], cd[tid * 3 + 1] * p);
        atomicAdd(&g_csum[r * 3 + 2], cd[tid * 3 + 2] * p);
        atomicAdd(&g_cnt[r], 1.0f);
    }
    // agg reduction: vectorized red.global.add.v4.f32, ef still in At
    {
        int cg = (tid & 63) * 4;  // column group start
        int e0 = tid >> 6;        // 0..3
#pragma unroll
        for (int it = 0; it < 16; it++) {
            int e = e0 + it * 4;
            float4 v = *(const float4*)(At + e * AS + cg);
            red4(&g_agg[(size_t)rows[e] * NF + cg], v);
        }
    }
}

// node MLP: h_out = h + Wn2 @ silu(Wn1 @ [h, agg] + bn1) + bn2
// Single A-tile: h-half (k 0..255), then agg-half (k 256..511), then hidden.
__global__ __launch_bounds__(THREADS, 2) void node_kernel(
    const float* __restrict__ h, const float* __restrict__ bn1,
    const float* __restrict__ bn2, float* __restrict__ out) {
    extern __shared__ float sm[];
    float* At = sm;
    float* Bs = At + TE * AS;
    int tid = threadIdx.x, ty = tid >> 4, tx = tid & 15;
    int nb = blockIdx.x * TE;
#pragma unroll
    for (int it = 0; it < 16; it++) {
        int l = tid + it * THREADS;
        int r = l >> 6, c4 = l & 63;
        int n = nb + r;
        float4 vh = (n < N_NODES) ? ((const float4*)(h + (size_t)n * NF))[c4]
                                  : make_float4(0.f, 0.f, 0.f, 0.f);
        *(float4*)(At + r * AS + c4 * 4) = vh;
    }
    ull acc[4][8];
    zero_acc(acc);
    gemm_acc(acc, g_Wn1T, At, NF, Bs, ty, tx);             // k = 0..255 (h part)
    __syncthreads();                                       // reads of h-tile done
#pragma unroll
    for (int it = 0; it < 16; it++) {
        int l = tid + it * THREADS;
        int r = l >> 6, c4 = l & 63;
        int n = nb + r;
        float4 va = (n < N_NODES) ? ((const float4*)(g_agg + (size_t)n * NF))[c4]
                                  : make_float4(0.f, 0.f, 0.f, 0.f);
        *(float4*)(At + r * AS + c4 * 4) = va;
    }
    gemm_acc(acc, g_Wn1T + NF * NF, At, NF, Bs, ty, tx);   // k = 256..511 (agg part)
    __syncthreads();                                       // reads of agg-tile done
    epi_store_silu(acc, bn1, At, ty, tx);                  // hidden into same tile
    zero_acc(acc);
    gemm_acc(acc, g_Wn2T, At, NF, Bs, ty, tx);             // leading sync covers writes
    epi_node_out(acc, bn2, h, out, nb, ty, tx);
}

__global__ void coord_kernel(const float* __restrict__ coord, float* __restrict__ out) {
    int n = blockIdx.x * blockDim.x + threadIdx.x;
    if (n >= N_NODES) return;
    float c = fmaxf(g_cnt[n], 1.0f);
    size_t base = (size_t)N_NODES * NF;
    out[base + n * 3 + 0] = coord[n * 3 + 0] + g_csum[n * 3 + 0] / c;
    out[base + n * 3 + 1] = coord[n * 3 + 1] + g_csum[n * 3 + 1] / c;
    out[base + n * 3 + 2] = coord[n * 3 + 2] + g_csum[n * 3 + 2] / c;
}

// ----------------------------- host -----------------------------
extern "C" void kernel_launch(void* const* d_in, const int* in_sizes, int n_in,
                              void* d_out, int out_size) {
    const float* h = (const float*)d_in[0];
    const int* ei = (const int*)d_in[1];
    const float* coord = (const float*)d_in[2];
    const float* We1 = (const float*)d_in[3];
    const float* be1 = (const float*)d_in[4];
    const float* We2 = (const float*)d_in[5];
    const float* be2 = (const float*)d_in[6];
    const float* Wn1 = (const float*)d_in[7];
    const float* bn1 = (const float*)d_in[8];
    const float* Wn2 = (const float*)d_in[9];
    const float* bn2 = (const float*)d_in[10];
    const float* Wc1 = (const float*)d_in[11];
    const float* bc1 = (const float*)d_in[12];
    const float* Wc2 = (const float*)d_in[13];
    float* out = (float*)d_out;

    const int EDGE_SMEM = (TE * AS + 8192 + 192 + 64 + 64 + 128) * 4 + 128;
    const int NODE_SMEM = (TE * AS + 8192) * 4;
    const int PQ_SMEM = (TE * AS + 8192) * 4;

    cudaFuncSetAttribute(edge_kernel, cudaFuncAttributeMaxDynamicSharedMemorySize, EDGE_SMEM);
    cudaFuncSetAttribute(node_kernel, cudaFuncAttributeMaxDynamicSharedMemorySize, NODE_SMEM);
    cudaFuncSetAttribute(pq_kernel, cudaFuncAttributeMaxDynamicSharedMemorySize, PQ_SMEM);

    zero_kernel<<<(N_NODES * NF / 4 + 255) / 256, 256>>>();
    prep_kernel<<<(512 * NF + 255) / 256, 256>>>(We1, We2, Wc1, Wn1, Wn2);
    pq_kernel<<<(N_NODES + TE - 1) / TE, THREADS, PQ_SMEM>>>(h);
    edge_kernel<<<N_EDGES / TE, THREADS, EDGE_SMEM>>>(ei, coord, be1, be2, bc1, Wc2);
    node_kernel<<<(N_NODES + TE - 1) / TE, THREADS, NODE_SMEM>>>(h, bn1, bn2, out);
    coord_kernel<<<(N_NODES + 255) / 256, 256>>>(coord, out);
}

// round 16
// speedup vs baseline: 1.8271x; 1.3912x over previous
#include <cuda_runtime.h>
#include <cuda_bf16.h>
#include <cstdint>

#define N_NODES 50000
#define N_EDGES 800000
#define NF 256
#define TE 64          // tile rows (pq/node fp32x2 kernels)
#define AS 260         // smem A row stride (words)
#define THREADS 256
#define TEE 64         // edge tile rows (mma kernel)
#define BS2 36         // B chunk row stride (words), conflict-free

typedef unsigned long long ull;

// ----------------------------- device scratch -----------------------------
__device__ __align__(16) float g_P[N_NODES * NF];
__device__ __align__(16) float g_Q[N_NODES * NF];
__device__ __align__(16) float g_agg[N_NODES * NF];
__device__ __align__(16) float g_csum[N_NODES * 3];
__device__ __align__(16) float g_cnt[N_NODES];
__device__ __align__(16) float g_We1aT[NF * NF];
__device__ __align__(16) float g_We1bT[NF * NF];
__device__ __align__(16) float g_we1last[NF];
__device__ __align__(16) float g_Wn1T[512 * NF];
__device__ __align__(16) float g_Wn2T[NF * NF];

// ----------------------------- helpers -----------------------------
__device__ __forceinline__ float silu(float x) {
    return x / (1.0f + __expf(-x));
}
__device__ __forceinline__ ull pack2(float x, float y) {
    ull r; asm("mov.b64 %0, {%1, %2};" : "=l"(r) : "f"(x), "f"(y)); return r;
}
__device__ __forceinline__ float2 unpack2(ull v) {
    float2 f; asm("mov.b64 {%0, %1}, %2;" : "=f"(f.x), "=f"(f.y) : "l"(v)); return f;
}
__device__ __forceinline__ void fma2(ull& acc, ull a, ull b) {
    asm("fma.rn.f32x2 %0, %1, %2, %0;" : "+l"(acc) : "l"(a), "l"(b));
}
__device__ __forceinline__ void red4(float* p, float4 v) {
    asm volatile("red.global.add.v4.f32 [%0], {%1, %2, %3, %4};"
                 :: "l"(p), "f"(v.x), "f"(v.y), "f"(v.z), "f"(v.w) : "memory");
}
__device__ __forceinline__ void zero_acc(ull acc[4][8]) {
#pragma unroll
    for (int i = 0; i < 4; i++)
#pragma unroll
        for (int j = 0; j < 8; j++) acc[i][j] = 0ull;
}
// tf32 round (rna) into b32 register
__device__ __forceinline__ uint32_t tf32r(float f) {
    uint32_t u; asm("cvt.rna.tf32.f32 %0, %1;" : "=r"(u) : "f"(f)); return u;
}
// m16n8k8 tf32 MMA (base ISA, sm_80+)
__device__ __forceinline__ void mma8(float c[4], uint32_t a0, uint32_t a1,
                                     uint32_t a2, uint32_t a3,
                                     uint32_t b0, uint32_t b1) {
    asm("mma.sync.aligned.m16n8k8.row.col.f32.tf32.tf32.f32 "
        "{%0,%1,%2,%3}, {%4,%5,%6,%7}, {%8,%9}, {%0,%1,%2,%3};"
        : "+f"(c[0]), "+f"(c[1]), "+f"(c[2]), "+f"(c[3])
        : "r"(a0), "r"(a1), "r"(a2), "r"(a3), "r"(b0), "r"(b1));
}

// ----------------------------- fp32x2 tile GEMM (pq/node) ------------------
__device__ __forceinline__ void gemm_acc(ull acc[4][8],
                                         const float* __restrict__ Bt,
                                         const float* As, int K,
                                         float* BsF, int ty, int tx) {
    const int tid = threadIdx.x;
    for (int kb = 0; kb < K; kb += 32) {
        __syncthreads();
        const float4* src = (const float4*)(Bt + kb * NF);
        float4* dst = (float4*)BsF;
#pragma unroll
        for (int it = 0; it < 8; it++) {
            int l = tid + it * THREADS;
            dst[l] = src[l];
        }
        __syncthreads();
        const ull* Bs2 = (const ull*)BsF;
#pragma unroll
        for (int k = 0; k < 32; k++) {
            ull a[4];
#pragma unroll
            for (int i = 0; i < 4; i++) {
                float av = As[(ty * 4 + i) * AS + kb + k];
                a[i] = pack2(av, av);
            }
#pragma unroll
            for (int jj = 0; jj < 8; jj++) {
                ull b = Bs2[k * 128 + jj * 16 + tx];
#pragma unroll
                for (int i = 0; i < 4; i++) fma2(acc[i][jj], a[i], b);
            }
        }
    }
}

__device__ __forceinline__ void epi_store_silu(ull acc[4][8],
                                               const float* __restrict__ bias,
                                               float* Cs, int ty, int tx) {
    const float2* b2 = (const float2*)bias;
#pragma unroll
    for (int i = 0; i < 4; i++) {
        int e = ty * 4 + i;
#pragma unroll
        for (int jj = 0; jj < 8; jj++) {
            int p = jj * 16 + tx;
            float2 v = unpack2(acc[i][jj]);
            float2 b = b2[p];
            ((float2*)(Cs + e * AS))[p] = make_float2(silu(v.x + b.x), silu(v.y + b.y));
        }
    }
}

__device__ __forceinline__ void epi_store_g(ull acc[4][8], float* __restrict__ Cg,
                                            int nb, int ty, int tx) {
#pragma unroll
    for (int i = 0; i < 4; i++) {
        int n = nb + ty * 4 + i;
        if (n < N_NODES) {
#pragma unroll
            for (int jj = 0; jj < 8; jj++) {
                int p = jj * 16 + tx;
                ((float2*)(Cg + (size_t)n * NF))[p] = unpack2(acc[i][jj]);
            }
        }
    }
}

__device__ __forceinline__ void epi_node_out(ull acc[4][8],
                                             const float* __restrict__ bn2,
                                             const float* __restrict__ h,
                                             float* __restrict__ out,
                                             int nb, int ty, int tx) {
    const float2* b2 = (const float2*)bn2;
#pragma unroll
    for (int i = 0; i < 4; i++) {
        int n = nb + ty * 4 + i;
        if (n < N_NODES) {
            const float2* h2 = (const float2*)(h + (size_t)n * NF);
            float2* o2 = (float2*)(out + (size_t)n * NF);
#pragma unroll
            for (int jj = 0; jj < 8; jj++) {
                int p = jj * 16 + tx;
                float2 v = unpack2(acc[i][jj]);
                float2 b = b2[p];
                float2 hh = h2[p];
                o2[p] = make_float2(v.x + b.x + hh.x, v.y + b.y + hh.y);
            }
        }
    }
}

// ----------------------------- small kernels -----------------------------
__global__ void zero_kernel() {
    int i = blockIdx.x * blockDim.x + threadIdx.x;
    int tot4 = (N_NODES * NF) / 4;
    if (i < tot4) ((float4*)g_agg)[i] = make_float4(0.f, 0.f, 0.f, 0.f);
    if (i < N_NODES) {
        g_cnt[i] = 0.f;
        g_csum[i * 3 + 0] = 0.f;
        g_csum[i * 3 + 1] = 0.f;
        g_csum[i * 3 + 2] = 0.f;
    }
}

__global__ void prep_kernel(const float* __restrict__ We1, const float* __restrict__ Wn1,
                            const float* __restrict__ Wn2) {
    int idx = blockIdx.x * blockDim.x + threadIdx.x;  // over 512*256
    if (idx >= 512 * NF) return;
    int k = idx / NF, c = idx % NF;
    if (k < NF) {
        g_We1aT[k * NF + c] = We1[c * 513 + k];
        g_We1bT[k * NF + c] = We1[c * 513 + NF + k];
        g_Wn2T[k * NF + c] = Wn2[c * NF + k];
        if (k == 0) g_we1last[c] = We1[c * 513 + 512];
    }
    g_Wn1T[k * NF + c] = Wn1[c * 512 + k];
}

// P = h @ We1a^T ; Q = h @ We1b^T  (fp32x2)
__global__ __launch_bounds__(THREADS, 2) void pq_kernel(const float* __restrict__ h) {
    extern __shared__ float sm[];
    float* At = sm;
    float* Bs = sm + TE * AS;
    int tid = threadIdx.x, ty = tid >> 4, tx = tid & 15;
    int nb = blockIdx.x * TE;
#pragma unroll
    for (int it = 0; it < 16; it++) {
        int l = tid + it * THREADS;
        int r = l >> 6, c4 = l & 63;
        int n = nb + r;
        float4 v = (n < N_NODES) ? ((const float4*)(h + (size_t)n * NF))[c4]
                                 : make_float4(0.f, 0.f, 0.f, 0.f);
        *(float4*)(At + r * AS + c4 * 4) = v;
    }
    ull acc[4][8];
    zero_acc(acc);
    gemm_acc(acc, g_We1aT, At, NF, Bs, ty, tx);
    epi_store_g(acc, g_P, nb, ty, tx);
    zero_acc(acc);
    gemm_acc(acc, g_We1bT, At, NF, Bs, ty, tx);
    epi_store_g(acc, g_Q, nb, ty, tx);
}

// ----------------------------- mma.sync tf32 edge kernel -----------------------------
// smem (floats): m[64*AS], Bs[256*BS2], cd[192], rad[64], phi[64],
//                rows[64], cols[64], be2S[256], bc1S[256], wc2S[256]
#define EDGE_SMEM_FLOATS (TEE * AS + 256 * BS2 + 192 + 64 + 64 + 64 + 64 + 256 + 256 + 256)

__global__ __launch_bounds__(THREADS, 2) void edge_kernel_mma(
    const int* __restrict__ ei, const float* __restrict__ coord,
    const float* __restrict__ We2, const float* __restrict__ Wc1,
    const float* __restrict__ be1, const float* __restrict__ be2,
    const float* __restrict__ bc1, const float* __restrict__ wc2) {
    extern __shared__ float sm[];
    float* mS = sm;                       // 64*AS (m, then ef)
    float* BsS = mS + TEE * AS;           // 256*BS2
    float* cdS = BsS + 256 * BS2;         // 192
    float* radS = cdS + 192;              // 64
    float* phiS = radS + 64;              // 64
    int* rowsS = (int*)(phiS + 64);       // 64
    int* colsS = rowsS + 64;              // 64
    float* be2S = (float*)(colsS + 64);   // 256
    float* bc1S = be2S + 256;             // 256
    float* wc2S = bc1S + 256;             // 256

    int tid = threadIdx.x, wid = tid >> 5, lane = tid & 31;
    int g = lane >> 2, t = lane & 3;
    int r0 = (wid >> 1) * 16;             // warp row base (0,16,32,48)
    int cg0 = (wid & 1) * 128;            // warp col base (0,128)
    int eb = blockIdx.x * TEE;

    be2S[tid] = be2[tid];
    bc1S[tid] = bc1[tid];
    wc2S[tid] = wc2[tid];
    if (tid < TEE) {
        int e = eb + tid;
        int r = ei[e], c = ei[N_EDGES + e];
        rowsS[tid] = r;
        colsS[tid] = c;
        float dx = coord[r * 3 + 0] - coord[c * 3 + 0];
        float dy = coord[r * 3 + 1] - coord[c * 3 + 1];
        float dz = coord[r * 3 + 2] - coord[c * 3 + 2];
        cdS[tid * 3 + 0] = dx;
        cdS[tid * 3 + 1] = dy;
        cdS[tid * 3 + 2] = dz;
        radS[tid] = dx * dx + dy * dy + dz * dz;
        phiS[tid] = 0.f;
    }
    __syncthreads();

    // stage m[e][c] = silu(P[row]+Q[col]+radial*we1last+be1), fp32
    {
        float wl = g_we1last[tid];
        float b1 = be1[tid];
#pragma unroll 8
        for (int e = 0; e < TEE; e++) {
            float val = g_P[(size_t)rowsS[e] * NF + tid] + g_Q[(size_t)colsS[e] * NF + tid]
                      + radS[e] * wl + b1;
            mS[e * AS + tid] = silu(val);
        }
    }

    float c[16][4];

    // ---------------- GEMM2: C = m @ We2^T  (A = mS fp32 -> tf32; B = We2[n][k]) ----
#pragma unroll
    for (int nt = 0; nt < 16; nt++)
#pragma unroll
        for (int j = 0; j < 4; j++) c[nt][j] = 0.f;

    for (int ch = 0; ch < 8; ch++) {
        __syncthreads();   // prior Bs consumers done / m writes visible (1st iter)
        {
            const float4* src = (const float4*)(We2 + (size_t)tid * NF + ch * 32);
            uint32_t* dst = (uint32_t*)(BsS + tid * BS2);
#pragma unroll
            for (int q = 0; q < 8; q++) {
                float4 v = src[q];
                dst[q * 4 + 0] = tf32r(v.x);
                dst[q * 4 + 1] = tf32r(v.y);
                dst[q * 4 + 2] = tf32r(v.z);
                dst[q * 4 + 3] = tf32r(v.w);
            }
        }
        __syncthreads();
#pragma unroll
        for (int k8 = 0; k8 < 4; k8++) {
            int kk = ch * 32 + k8 * 8;
            uint32_t a0 = tf32r(mS[(r0 + g) * AS + kk + t]);
            uint32_t a1 = tf32r(mS[(r0 + g + 8) * AS + kk + t]);
            uint32_t a2 = tf32r(mS[(r0 + g) * AS + kk + t + 4]);
            uint32_t a3 = tf32r(mS[(r0 + g + 8) * AS + kk + t + 4]);
            const uint32_t* Bu = (const uint32_t*)BsS;
#pragma unroll
            for (int nt = 0; nt < 16; nt++) {
                int n = cg0 + nt * 8 + g;
                uint32_t b0 = Bu[n * BS2 + k8 * 8 + t];
                uint32_t b1 = Bu[n * BS2 + k8 * 8 + t + 4];
                mma8(c[nt], a0, a1, a2, a3, b0, b1);
            }
        }
    }
    __syncthreads();  // all m reads done before ef overwrite

    // epilogue: ef = silu(C + be2) -> mS (fp32), same layout
#pragma unroll
    for (int nt = 0; nt < 16; nt++) {
        int col = cg0 + nt * 8 + 2 * t;
        float2 v0 = make_float2(silu(c[nt][0] + be2S[col]), silu(c[nt][1] + be2S[col + 1]));
        float2 v1 = make_float2(silu(c[nt][2] + be2S[col]), silu(c[nt][3] + be2S[col + 1]));
        *(float2*)&mS[(r0 + g) * AS + col] = v0;
        *(float2*)&mS[(r0 + g + 8) * AS + col] = v1;
    }
    __syncthreads();

    // agg reduction (ef fp32 in mS)
    {
        int cg = (tid & 63) * 4;
        int e0 = tid >> 6;
#pragma unroll
        for (int it = 0; it < 16; it++) {
            int e = e0 + it * 4;
            float4 v = *(const float4*)&mS[e * AS + cg];
            red4(&g_agg[(size_t)rowsS[e] * NF + cg], v);
        }
    }

    // ---------------- GEMM3: C = ef @ Wc1^T ----------------
#pragma unroll
    for (int nt = 0; nt < 16; nt++)
#pragma unroll
        for (int j = 0; j < 4; j++) c[nt][j] = 0.f;

    for (int ch = 0; ch < 8; ch++) {
        __syncthreads();
        {
            const float4* src = (const float4*)(Wc1 + (size_t)tid * NF + ch * 32);
            uint32_t* dst = (uint32_t*)(BsS + tid * BS2);
#pragma unroll
            for (int q = 0; q < 8; q++) {
                float4 v = src[q];
                dst[q * 4 + 0] = tf32r(v.x);
                dst[q * 4 + 1] = tf32r(v.y);
                dst[q * 4 + 2] = tf32r(v.z);
                dst[q * 4 + 3] = tf32r(v.w);
            }
        }
        __syncthreads();
#pragma unroll
        for (int k8 = 0; k8 < 4; k8++) {
            int kk = ch * 32 + k8 * 8;
            uint32_t a0 = tf32r(mS[(r0 + g) * AS + kk + t]);
            uint32_t a1 = tf32r(mS[(r0 + g + 8) * AS + kk + t]);
            uint32_t a2 = tf32r(mS[(r0 + g) * AS + kk + t + 4]);
            uint32_t a3 = tf32r(mS[(r0 + g + 8) * AS + kk + t + 4]);
            const uint32_t* Bu = (const uint32_t*)BsS;
#pragma unroll
            for (int nt = 0; nt < 16; nt++) {
                int n = cg0 + nt * 8 + g;
                uint32_t b0 = Bu[n * BS2 + k8 * 8 + t];
                uint32_t b1 = Bu[n * BS2 + k8 * 8 + t + 4];
                mma8(c[nt], a0, a1, a2, a3, b0, b1);
            }
        }
    }

    // phi epilogue: phi[row] += sum_c silu(C + bc1[c]) * wc2[c]
    {
        float s0 = 0.f, s1 = 0.f;
#pragma unroll
        for (int nt = 0; nt < 16; nt++) {
            int col = cg0 + nt * 8 + 2 * t;
            s0 += silu(c[nt][0] + bc1S[col]) * wc2S[col]
                + silu(c[nt][1] + bc1S[col + 1]) * wc2S[col + 1];
            s1 += silu(c[nt][2] + bc1S[col]) * wc2S[col]
                + silu(c[nt][3] + bc1S[col + 1]) * wc2S[col + 1];
        }
        atomicAdd(&phiS[r0 + g], s0);
        atomicAdd(&phiS[r0 + g + 8], s1);
    }
    __syncthreads();

    // coord trans atomics
    if (tid < TEE) {
        float p = phiS[tid];
        int r = rowsS[tid];
        atomicAdd(&g_csum[r * 3 + 0], cdS[tid * 3 + 0] * p);
        atomicAdd(&g_csum[r * 3 + 1], cdS[tid * 3 + 1] * p);
        atomicAdd(&g_csum[r * 3 + 2], cdS[tid * 3 + 2] * p);
        atomicAdd(&g_cnt[r], 1.0f);
    }
}

// node MLP (fp32x2): h_out = h + Wn2 @ silu(Wn1 @ [h, agg] + bn1) + bn2
__global__ __launch_bounds__(THREADS, 2) void node_kernel(
    const float* __restrict__ h, const float* __restrict__ bn1,
    const float* __restrict__ bn2, float* __restrict__ out) {
    extern __shared__ float sm[];
    float* At = sm;
    float* Bs = At + TE * AS;
    int tid = threadIdx.x, ty = tid >> 4, tx = tid & 15;
    int nb = blockIdx.x * TE;
#pragma unroll
    for (int it = 0; it < 16; it++) {
        int l = tid + it * THREADS;
        int r = l >> 6, c4 = l & 63;
        int n = nb + r;
        float4 vh = (n < N_NODES) ? ((const float4*)(h + (size_t)n * NF))[c4]
                                  : make_float4(0.f, 0.f, 0.f, 0.f);
        *(float4*)(At + r * AS + c4 * 4) = vh;
    }
    ull acc[4][8];
    zero_acc(acc);
    gemm_acc(acc, g_Wn1T, At, NF, Bs, ty, tx);
    __syncthreads();
#pragma unroll
    for (int it = 0; it < 16; it++) {
        int l = tid + it * THREADS;
        int r = l >> 6, c4 = l & 63;
        int n = nb + r;
        float4 va = (n < N_NODES) ? ((const float4*)(g_agg + (size_t)n * NF))[c4]
                                  : make_float4(0.f, 0.f, 0.f, 0.f);
        *(float4*)(At + r * AS + c4 * 4) = va;
    }
    gemm_acc(acc, g_Wn1T + NF * NF, At, NF, Bs, ty, tx);
    __syncthreads();
    epi_store_silu(acc, bn1, At, ty, tx);
    zero_acc(acc);
    gemm_acc(acc, g_Wn2T, At, NF, Bs, ty, tx);
    epi_node_out(acc, bn2, h, out, nb, ty, tx);
}

__global__ void coord_kernel(const float* __restrict__ coord, float* __restrict__ out) {
    int n = blockIdx.x * blockDim.x + threadIdx.x;
    if (n >= N_NODES) return;
    float c = fmaxf(g_cnt[n], 1.0f);
    size_t base = (size_t)N_NODES * NF;
    out[base + n * 3 + 0] = coord[n * 3 + 0] + g_csum[n * 3 + 0] / c;
    out[base + n * 3 + 1] = coord[n * 3 + 1] + g_csum[n * 3 + 1] / c;
    out[base + n * 3 + 2] = coord[n * 3 + 2] + g_csum[n * 3 + 2] / c;
}

// ----------------------------- host -----------------------------
extern "C" void kernel_launch(void* const* d_in, const int* in_sizes, int n_in,
                              void* d_out, int out_size) {
    const float* h = (const float*)d_in[0];
    const int* ei = (const int*)d_in[1];
    const float* coord = (const float*)d_in[2];
    const float* We1 = (const float*)d_in[3];
    const float* be1 = (const float*)d_in[4];
    const float* We2 = (const float*)d_in[5];
    const float* be2 = (const float*)d_in[6];
    const float* Wn1 = (const float*)d_in[7];
    const float* bn1 = (const float*)d_in[8];
    const float* Wn2 = (const float*)d_in[9];
    const float* bn2 = (const float*)d_in[10];
    const float* Wc1 = (const float*)d_in[11];
    const float* bc1 = (const float*)d_in[12];
    const float* Wc2 = (const float*)d_in[13];
    float* out = (float*)d_out;

    const int EDGE_SMEM = EDGE_SMEM_FLOATS * 4;
    const int NODE_SMEM = (TE * AS + 8192) * 4;
    const int PQ_SMEM = (TE * AS + 8192) * 4;

    cudaFuncSetAttribute(edge_kernel_mma, cudaFuncAttributeMaxDynamicSharedMemorySize, EDGE_SMEM);
    cudaFuncSetAttribute(node_kernel, cudaFuncAttributeMaxDynamicSharedMemorySize, NODE_SMEM);
    cudaFuncSetAttribute(pq_kernel, cudaFuncAttributeMaxDynamicSharedMemorySize, PQ_SMEM);

    zero_kernel<<<(N_NODES * NF / 4 + 255) / 256, 256>>>();
    prep_kernel<<<(512 * NF + 255) / 256, 256>>>(We1, Wn1, Wn2);
    pq_kernel<<<(N_NODES + TE - 1) / TE, THREADS, PQ_SMEM>>>(h);
    edge_kernel_mma<<<N_EDGES / TEE, THREADS, EDGE_SMEM>>>(ei, coord, We2, Wc1,
                                                           be1, be2, bc1, Wc2);
    node_kernel<<<(N_NODES + TE - 1) / TE, THREADS, NODE_SMEM>>>(h, bn1, bn2, out);
    coord_kernel<<<(N_NODES + 255) / 256, 256>>>(coord, out);
}